// round 1
// baseline (speedup 1.0000x reference)
#include <cuda_runtime.h>
#include <cuda_bf16.h>

// Problem constants
#define BB 2
#define TT 2048
#define CC 1024
#define HH 16
#define HD 64
#define ROWS (BB*TT)          // 4096
#define C3 (3*CC)             // 3072

// Scratch (allocation-free: __device__ globals)
__device__ float g_qkv[(size_t)ROWS * C3];   // [4096, 3072]  q|k|v
__device__ float g_att[(size_t)ROWS * CC];   // [4096, 1024]  attention output (b,t,(h,d))

// ---------------------------------------------------------------------------
// Tiled SGEMM: C[M,N] = A[M,K] @ B[K,N], row-major, M%64==0, N%64==0, K%16==0
// BM=BN=64, BK=16, 256 threads, 4x4 microtile
// ---------------------------------------------------------------------------
__global__ __launch_bounds__(256) void sgemm64(const float* __restrict__ A,
                                               const float* __restrict__ B,
                                               float* __restrict__ C,
                                               int M, int N, int K) {
    __shared__ float As[16][64];   // [k][m]
    __shared__ float Bs[16][64];   // [k][n]

    const int tid = threadIdx.x;
    const int tx = tid & 15;       // 0..15 -> n
    const int ty = tid >> 4;       // 0..15 -> m
    const int row0 = blockIdx.y * 64;
    const int col0 = blockIdx.x * 64;

    // A-load mapping: one float4 along K per thread
    const int am = tid >> 2;           // 0..63
    const int ak = (tid & 3) * 4;      // 0,4,8,12
    // B-load mapping: one float4 along N per thread
    const int bk = tid >> 4;           // 0..15
    const int bn = (tid & 15) * 4;     // 0..60

    float acc[4][4] = {};

    for (int k0 = 0; k0 < K; k0 += 16) {
        float4 av = *(const float4*)&A[(size_t)(row0 + am) * K + k0 + ak];
        float4 bv = *(const float4*)&B[(size_t)(k0 + bk) * N + col0 + bn];
        As[ak + 0][am] = av.x;
        As[ak + 1][am] = av.y;
        As[ak + 2][am] = av.z;
        As[ak + 3][am] = av.w;
        *(float4*)&Bs[bk][bn] = bv;
        __syncthreads();

        #pragma unroll
        for (int k = 0; k < 16; k++) {
            float4 a = *(const float4*)&As[k][ty * 4];
            float4 b = *(const float4*)&Bs[k][tx * 4];
            float ar[4] = {a.x, a.y, a.z, a.w};
            float br[4] = {b.x, b.y, b.z, b.w};
            #pragma unroll
            for (int i = 0; i < 4; i++)
                #pragma unroll
                for (int j = 0; j < 4; j++)
                    acc[i][j] = fmaf(ar[i], br[j], acc[i][j]);
        }
        __syncthreads();
    }

    #pragma unroll
    for (int i = 0; i < 4; i++) {
        float4 v = make_float4(acc[i][0], acc[i][1], acc[i][2], acc[i][3]);
        *(float4*)&C[(size_t)(row0 + ty * 4 + i) * N + col0 + tx * 4] = v;
    }
}

// ---------------------------------------------------------------------------
// Causal flash attention, fp32.
// grid: (B*H = 32, T/128 = 16), 128 threads; one thread = one query row.
// q, o live in registers (64 each); K/V tiles (64x64) staged in smem and read
// broadcast by all threads. Online softmax with rare-max rescale.
// ---------------------------------------------------------------------------
__global__ __launch_bounds__(128) void attn_kernel(const float* __restrict__ qkv,
                                                   float* __restrict__ out) {
    const int b = blockIdx.x >> 4;
    const int h = blockIdx.x & 15;
    const int t = blockIdx.y * 128 + threadIdx.x;   // global query index
    const float scale = 0.03125f;                   // 1024^-0.5

    __shared__ float Ks[64][64];
    __shared__ float Vs[64][64];

    const size_t qbase = ((size_t)(b * TT + t)) * C3 + h * HD;
    float q[HD], o[HD];
    #pragma unroll
    for (int d = 0; d < HD; d++) { q[d] = qkv[qbase + d] * scale; o[d] = 0.f; }
    float m = -1e30f, l = 0.f;

    const int ntiles = (blockIdx.y * 128 + 128) / 64;   // causal: only tiles up to block end
    for (int tile = 0; tile < ntiles; tile++) {
        const int j0 = tile * 64;
        __syncthreads();
        // cooperative K/V tile load: 64x64 floats each, 8 float4 per thread per tile
        #pragma unroll
        for (int i = 0; i < 8; i++) {
            int idx = threadIdx.x + i * 128;
            int r = idx >> 4;
            int c = (idx & 15) * 4;
            size_t g = ((size_t)(b * TT + j0 + r)) * C3 + h * HD + c;
            *(float4*)&Ks[r][c] = *(const float4*)&qkv[g + CC];
            *(float4*)&Vs[r][c] = *(const float4*)&qkv[g + 2 * CC];
        }
        __syncthreads();

        int jmax = t - j0 + 1;
        if (jmax > 64) jmax = 64;
        for (int j = 0; j < jmax; j++) {
            // s = q . K[j]  (4-way split accumulators for ILP)
            float s0 = 0.f, s1 = 0.f, s2 = 0.f, s3 = 0.f;
            #pragma unroll
            for (int d = 0; d < HD; d += 4) {
                s0 = fmaf(q[d + 0], Ks[j][d + 0], s0);
                s1 = fmaf(q[d + 1], Ks[j][d + 1], s1);
                s2 = fmaf(q[d + 2], Ks[j][d + 2], s2);
                s3 = fmaf(q[d + 3], Ks[j][d + 3], s3);
            }
            float s = (s0 + s1) + (s2 + s3);
            if (s > m) {               // rare rescale path
                float corr = __expf(m - s);
                l *= corr;
                #pragma unroll
                for (int d = 0; d < HD; d++) o[d] *= corr;
                m = s;
            }
            float p = __expf(s - m);
            l += p;
            #pragma unroll
            for (int d = 0; d < HD; d++) o[d] = fmaf(p, Vs[j][d], o[d]);
        }
    }

    const float inv = 1.f / l;
    const size_t ob = ((size_t)(b * TT + t)) * CC + h * HD;
    #pragma unroll
    for (int d = 0; d < HD; d++) out[ob + d] = o[d] * inv;
}

// ---------------------------------------------------------------------------
extern "C" void kernel_launch(void* const* d_in, const int* in_sizes, int n_in,
                              void* d_out, int out_size) {
    const float* x    = (const float*)d_in[0];   // [2,2048,1024]
    const float* Wqkv = (const float*)d_in[1];   // [1024,3072]
    const float* Wo   = (const float*)d_in[2];   // [1024,1024]
    float* out = (float*)d_out;                  // [2,2048,1024]

    float* qkv;  cudaGetSymbolAddress((void**)&qkv, g_qkv);
    float* att;  cudaGetSymbolAddress((void**)&att, g_att);

    // 1) qkv = x @ Wqkv   [4096,3072]
    sgemm64<<<dim3(C3 / 64, ROWS / 64), 256>>>(x, Wqkv, qkv, ROWS, C3, CC);
    // 2) causal attention -> att [4096,1024]
    attn_kernel<<<dim3(BB * HH, TT / 128), 128>>>(qkv, att);
    // 3) out = att @ Wo   [4096,1024]
    sgemm64<<<dim3(CC / 64, ROWS / 64), 256>>>(att, Wo, out, ROWS, CC, CC);
}

// round 2
// speedup vs baseline: 1.5565x; 1.5565x over previous
#include <cuda_runtime.h>
#include <cuda_bf16.h>
#include <cstdint>

// Problem constants
#define BB 2
#define TT 2048
#define CC 1024
#define HH 16
#define HD 64
#define ROWS (BB*TT)          // 4096
#define C3 (3*CC)             // 3072

// Scratch (allocation-free: __device__ globals)
__device__ float g_qkv[(size_t)ROWS * C3];   // [4096, 3072]  q|k|v
__device__ float g_att[(size_t)ROWS * CC];   // [4096, 1024]  attention output

// ---------------------------------------------------------------------------
// tf32 helpers
// ---------------------------------------------------------------------------
__device__ __forceinline__ float to_tf32(float x) {
    float y;
    asm("cvt.rna.tf32.f32 %0, %1;" : "=f"(y) : "f"(x));
    return y;
}

__device__ __forceinline__ void mma_tf32(float& d0, float& d1, float& d2, float& d3,
                                         float a0, float a1, float a2, float a3,
                                         float b0, float b1) {
    asm volatile(
        "mma.sync.aligned.m16n8k8.row.col.f32.tf32.tf32.f32 "
        "{%0,%1,%2,%3}, {%4,%5,%6,%7}, {%8,%9}, {%0,%1,%2,%3};"
        : "+f"(d0), "+f"(d1), "+f"(d2), "+f"(d3)
        : "r"(__float_as_uint(a0)), "r"(__float_as_uint(a1)),
          "r"(__float_as_uint(a2)), "r"(__float_as_uint(a3)),
          "r"(__float_as_uint(b0)), "r"(__float_as_uint(b1)));
}

// ---------------------------------------------------------------------------
// tf32 tensor-core GEMM: C[M,N] = A[M,K] @ B[K,N], row-major.
// Block tile 128x128, K-tile 32, 256 threads = 8 warps (2m x 4n),
// warp tile 64m x 32n, mma m16n8k8.
// As[128][40]: row-major m,k  (stride 40 -> frag loads <=2-way conflict)
// Bs[32][136]: k,n            (stride 136 = 8 mod 32 -> conflict-free frags)
// Requires M%128==0, N%128==0, K%32==0.
// ---------------------------------------------------------------------------
#define ASTR 40
#define BSTR 136

__global__ __launch_bounds__(256) void tgemm(const float* __restrict__ A,
                                             const float* __restrict__ B,
                                             float* __restrict__ C,
                                             int M, int N, int K) {
    __shared__ float As[128 * ASTR];
    __shared__ float Bs[32 * BSTR];

    const int tid  = threadIdx.x;
    const int warp = tid >> 5;
    const int lane = tid & 31;
    const int g = lane >> 2;      // 0..7  (row group)
    const int t = lane & 3;       // 0..3  (k group)

    const int wm = (warp >> 2) * 64;   // warp m offset within block
    const int wn = (warp & 3) * 32;    // warp n offset within block

    const int row0 = blockIdx.y * 128;
    const int col0 = blockIdx.x * 128;

    // staging maps
    const int a_m  = tid >> 3;          // 0..31 (+32*i)
    const int a_k4 = (tid & 7) * 4;     // 0,4,...,28
    const int b_k  = tid >> 5;          // 0..7  (+8*i)
    const int b_n4 = (tid & 31) * 4;    // 0..124

    float acc[4][4][4];                 // [mt][nt][4]
    #pragma unroll
    for (int i = 0; i < 4; i++)
        #pragma unroll
        for (int j = 0; j < 4; j++)
            #pragma unroll
            for (int r = 0; r < 4; r++) acc[i][j][r] = 0.f;

    for (int kt = 0; kt < K; kt += 32) {
        // ---- stage A tile (128 x 32), converted to tf32 ----
        #pragma unroll
        for (int i = 0; i < 4; i++) {
            int m = a_m + 32 * i;
            float4 v = *(const float4*)&A[(size_t)(row0 + m) * K + kt + a_k4];
            As[m * ASTR + a_k4 + 0] = to_tf32(v.x);
            As[m * ASTR + a_k4 + 1] = to_tf32(v.y);
            As[m * ASTR + a_k4 + 2] = to_tf32(v.z);
            As[m * ASTR + a_k4 + 3] = to_tf32(v.w);
        }
        // ---- stage B tile (32 x 128), converted to tf32 ----
        #pragma unroll
        for (int i = 0; i < 4; i++) {
            int k = b_k + 8 * i;
            float4 v = *(const float4*)&B[(size_t)(kt + k) * N + col0 + b_n4];
            v.x = to_tf32(v.x); v.y = to_tf32(v.y);
            v.z = to_tf32(v.z); v.w = to_tf32(v.w);
            *(float4*)&Bs[k * BSTR + b_n4] = v;
        }
        __syncthreads();

        #pragma unroll
        for (int ks = 0; ks < 4; ks++) {
            const int k0 = ks * 8;
            // A fragments: 4 m-tiles
            float af[4][4];
            #pragma unroll
            for (int mt = 0; mt < 4; mt++) {
                int r = wm + mt * 16 + g;
                af[mt][0] = As[(r    ) * ASTR + k0 + t];
                af[mt][1] = As[(r + 8) * ASTR + k0 + t];
                af[mt][2] = As[(r    ) * ASTR + k0 + t + 4];
                af[mt][3] = As[(r + 8) * ASTR + k0 + t + 4];
            }
            // B fragments: 4 n-tiles
            float bf[4][2];
            #pragma unroll
            for (int nt = 0; nt < 4; nt++) {
                int c = wn + nt * 8 + g;
                bf[nt][0] = Bs[(k0 + t    ) * BSTR + c];
                bf[nt][1] = Bs[(k0 + t + 4) * BSTR + c];
            }
            #pragma unroll
            for (int mt = 0; mt < 4; mt++)
                #pragma unroll
                for (int nt = 0; nt < 4; nt++)
                    mma_tf32(acc[mt][nt][0], acc[mt][nt][1], acc[mt][nt][2], acc[mt][nt][3],
                             af[mt][0], af[mt][1], af[mt][2], af[mt][3],
                             bf[nt][0], bf[nt][1]);
        }
        __syncthreads();
    }

    // ---- epilogue ----
    #pragma unroll
    for (int mt = 0; mt < 4; mt++) {
        int r = row0 + wm + mt * 16 + g;
        #pragma unroll
        for (int nt = 0; nt < 4; nt++) {
            int c = col0 + wn + nt * 8 + 2 * t;
            *(float2*)&C[(size_t)r * N + c]       = make_float2(acc[mt][nt][0], acc[mt][nt][1]);
            *(float2*)&C[(size_t)(r + 8) * N + c] = make_float2(acc[mt][nt][2], acc[mt][nt][3]);
        }
    }
}

// ---------------------------------------------------------------------------
// Causal flash attention, fp32 (unchanged from R1 — proven correct).
// grid: (B*H = 32, T/128 = 16), 128 threads; one thread = one query row.
// ---------------------------------------------------------------------------
__global__ __launch_bounds__(128) void attn_kernel(const float* __restrict__ qkv,
                                                   float* __restrict__ out) {
    const int b = blockIdx.x >> 4;
    const int h = blockIdx.x & 15;
    const int t = blockIdx.y * 128 + threadIdx.x;   // global query index
    const float scale = 0.03125f;                   // 1024^-0.5

    __shared__ float Ks[64][64];
    __shared__ float Vs[64][64];

    const size_t qbase = ((size_t)(b * TT + t)) * C3 + h * HD;
    float q[HD], o[HD];
    #pragma unroll
    for (int d = 0; d < HD; d++) { q[d] = qkv[qbase + d] * scale; o[d] = 0.f; }
    float m = -1e30f, l = 0.f;

    const int ntiles = (blockIdx.y * 128 + 128) / 64;
    for (int tile = 0; tile < ntiles; tile++) {
        const int j0 = tile * 64;
        __syncthreads();
        #pragma unroll
        for (int i = 0; i < 8; i++) {
            int idx = threadIdx.x + i * 128;
            int r = idx >> 4;
            int c = (idx & 15) * 4;
            size_t gaddr = ((size_t)(b * TT + j0 + r)) * C3 + h * HD + c;
            *(float4*)&Ks[r][c] = *(const float4*)&qkv[gaddr + CC];
            *(float4*)&Vs[r][c] = *(const float4*)&qkv[gaddr + 2 * CC];
        }
        __syncthreads();

        int jmax = t - j0 + 1;
        if (jmax > 64) jmax = 64;
        for (int j = 0; j < jmax; j++) {
            float s0 = 0.f, s1 = 0.f, s2 = 0.f, s3 = 0.f;
            #pragma unroll
            for (int d = 0; d < HD; d += 4) {
                s0 = fmaf(q[d + 0], Ks[j][d + 0], s0);
                s1 = fmaf(q[d + 1], Ks[j][d + 1], s1);
                s2 = fmaf(q[d + 2], Ks[j][d + 2], s2);
                s3 = fmaf(q[d + 3], Ks[j][d + 3], s3);
            }
            float s = (s0 + s1) + (s2 + s3);
            if (s > m) {
                float corr = __expf(m - s);
                l *= corr;
                #pragma unroll
                for (int d = 0; d < HD; d++) o[d] *= corr;
                m = s;
            }
            float p = __expf(s - m);
            l += p;
            #pragma unroll
            for (int d = 0; d < HD; d++) o[d] = fmaf(p, Vs[j][d], o[d]);
        }
    }

    const float inv = 1.f / l;
    const size_t ob = ((size_t)(b * TT + t)) * CC + h * HD;
    #pragma unroll
    for (int d = 0; d < HD; d++) out[ob + d] = o[d] * inv;
}

// ---------------------------------------------------------------------------
extern "C" void kernel_launch(void* const* d_in, const int* in_sizes, int n_in,
                              void* d_out, int out_size) {
    const float* x    = (const float*)d_in[0];   // [2,2048,1024]
    const float* Wqkv = (const float*)d_in[1];   // [1024,3072]
    const float* Wo   = (const float*)d_in[2];   // [1024,1024]
    float* out = (float*)d_out;                  // [2,2048,1024]

    float* qkv;  cudaGetSymbolAddress((void**)&qkv, g_qkv);
    float* att;  cudaGetSymbolAddress((void**)&att, g_att);

    // 1) qkv = x @ Wqkv   [4096,3072]
    tgemm<<<dim3(C3 / 128, ROWS / 128), 256>>>(x, Wqkv, qkv, ROWS, C3, CC);
    // 2) causal attention -> att [4096,1024]
    attn_kernel<<<dim3(BB * HH, TT / 128), 128>>>(qkv, att);
    // 3) out = att @ Wo   [4096,1024]
    tgemm<<<dim3(CC / 128, ROWS / 128), 256>>>(att, Wo, out, ROWS, CC, CC);
}

// round 3
// speedup vs baseline: 3.3805x; 2.1718x over previous
#include <cuda_runtime.h>
#include <cuda_bf16.h>
#include <cstdint>

// Problem constants
#define BB 2
#define TT 2048
#define CC 1024
#define HH 16
#define HD 64
#define ROWS (BB*TT)          // 4096
#define C3 (3*CC)             // 3072

// Scratch (allocation-free: __device__ globals)
__device__ float g_qkv[(size_t)ROWS * C3];   // [4096, 3072]  q|k|v
__device__ float g_att[(size_t)ROWS * CC];   // [4096, 1024]

// ---------------------------------------------------------------------------
// tf32 helpers
// ---------------------------------------------------------------------------
__device__ __forceinline__ float to_tf32(float x) {
    float y;
    asm("cvt.rna.tf32.f32 %0, %1;" : "=f"(y) : "f"(x));
    return y;
}

__device__ __forceinline__ void mma_tf32(float& d0, float& d1, float& d2, float& d3,
                                         float a0, float a1, float a2, float a3,
                                         float b0, float b1) {
    asm volatile(
        "mma.sync.aligned.m16n8k8.row.col.f32.tf32.tf32.f32 "
        "{%0,%1,%2,%3}, {%4,%5,%6,%7}, {%8,%9}, {%0,%1,%2,%3};"
        : "+f"(d0), "+f"(d1), "+f"(d2), "+f"(d3)
        : "r"(__float_as_uint(a0)), "r"(__float_as_uint(a1)),
          "r"(__float_as_uint(a2)), "r"(__float_as_uint(a3)),
          "r"(__float_as_uint(b0)), "r"(__float_as_uint(b1)));
}

// ---------------------------------------------------------------------------
// tf32 tensor-core GEMM (unchanged from R2)
// ---------------------------------------------------------------------------
#define ASTR 40
#define BSTR 136

__global__ __launch_bounds__(256) void tgemm(const float* __restrict__ A,
                                             const float* __restrict__ B,
                                             float* __restrict__ C,
                                             int M, int N, int K) {
    __shared__ float As[128 * ASTR];
    __shared__ float Bs[32 * BSTR];

    const int tid  = threadIdx.x;
    const int warp = tid >> 5;
    const int lane = tid & 31;
    const int g = lane >> 2;
    const int t = lane & 3;

    const int wm = (warp >> 2) * 64;
    const int wn = (warp & 3) * 32;

    const int row0 = blockIdx.y * 128;
    const int col0 = blockIdx.x * 128;

    const int a_m  = tid >> 3;
    const int a_k4 = (tid & 7) * 4;
    const int b_k  = tid >> 5;
    const int b_n4 = (tid & 31) * 4;

    float acc[4][4][4];
    #pragma unroll
    for (int i = 0; i < 4; i++)
        #pragma unroll
        for (int j = 0; j < 4; j++)
            #pragma unroll
            for (int r = 0; r < 4; r++) acc[i][j][r] = 0.f;

    for (int kt = 0; kt < K; kt += 32) {
        #pragma unroll
        for (int i = 0; i < 4; i++) {
            int m = a_m + 32 * i;
            float4 v = *(const float4*)&A[(size_t)(row0 + m) * K + kt + a_k4];
            As[m * ASTR + a_k4 + 0] = to_tf32(v.x);
            As[m * ASTR + a_k4 + 1] = to_tf32(v.y);
            As[m * ASTR + a_k4 + 2] = to_tf32(v.z);
            As[m * ASTR + a_k4 + 3] = to_tf32(v.w);
        }
        #pragma unroll
        for (int i = 0; i < 4; i++) {
            int k = b_k + 8 * i;
            float4 v = *(const float4*)&B[(size_t)(kt + k) * N + col0 + b_n4];
            v.x = to_tf32(v.x); v.y = to_tf32(v.y);
            v.z = to_tf32(v.z); v.w = to_tf32(v.w);
            *(float4*)&Bs[k * BSTR + b_n4] = v;
        }
        __syncthreads();

        #pragma unroll
        for (int ks = 0; ks < 4; ks++) {
            const int k0 = ks * 8;
            float af[4][4];
            #pragma unroll
            for (int mt = 0; mt < 4; mt++) {
                int r = wm + mt * 16 + g;
                af[mt][0] = As[(r    ) * ASTR + k0 + t];
                af[mt][1] = As[(r + 8) * ASTR + k0 + t];
                af[mt][2] = As[(r    ) * ASTR + k0 + t + 4];
                af[mt][3] = As[(r + 8) * ASTR + k0 + t + 4];
            }
            float bf[4][2];
            #pragma unroll
            for (int nt = 0; nt < 4; nt++) {
                int c = wn + nt * 8 + g;
                bf[nt][0] = Bs[(k0 + t    ) * BSTR + c];
                bf[nt][1] = Bs[(k0 + t + 4) * BSTR + c];
            }
            #pragma unroll
            for (int mt = 0; mt < 4; mt++)
                #pragma unroll
                for (int nt = 0; nt < 4; nt++)
                    mma_tf32(acc[mt][nt][0], acc[mt][nt][1], acc[mt][nt][2], acc[mt][nt][3],
                             af[mt][0], af[mt][1], af[mt][2], af[mt][3],
                             bf[nt][0], bf[nt][1]);
        }
        __syncthreads();
    }

    #pragma unroll
    for (int mt = 0; mt < 4; mt++) {
        int r = row0 + wm + mt * 16 + g;
        #pragma unroll
        for (int nt = 0; nt < 4; nt++) {
            int c = col0 + wn + nt * 8 + 2 * t;
            *(float2*)&C[(size_t)r * N + c]       = make_float2(acc[mt][nt][0], acc[mt][nt][1]);
            *(float2*)&C[(size_t)(r + 8) * N + c] = make_float2(acc[mt][nt][2], acc[mt][nt][3]);
        }
    }
}

// ---------------------------------------------------------------------------
// Tensor-core causal flash attention (tf32 mma).
// Block: 128 query rows of one (b,h); 8 warps x 16 rows. Key tiles of 64.
// Smem layouts (stride AST=68 floats):
//   Ks [64 keys][d-permuted 64]   : B operand of S = Q K^T
//   Vts[64 d   ][key-permuted 64] : B operand of O += P V (V transposed)
//   Ps [128 row][key-permuted 64] : A operand of O += P V
// Column permutation within each 8-group: d -> (d&~7) + 2*(d&3) + ((d>>2)&1),
// so each mma fragment pair (k=t, k=t+4) is one aligned float2 LDS, and the
// lane->bank map (4g+2t) is conflict-free.
// ---------------------------------------------------------------------------
#define AST 68

__global__ __launch_bounds__(256) void attn_tc(const float* __restrict__ qkv,
                                               float* __restrict__ out) {
    extern __shared__ float sm[];
    float* Ks  = sm;                   // 64*AST
    float* Vts = sm + 64 * AST;        // 64*AST
    float* Ps  = sm + 128 * AST;       // 128*AST

    const int b   = blockIdx.x >> 4;
    const int h   = blockIdx.x & 15;
    const int qb  = (gridDim.y - 1) - blockIdx.y;   // heavy blocks first
    const int qt0 = qb * 128;
    const int tid  = threadIdx.x;
    const int warp = tid >> 5;
    const int lane = tid & 31;
    const int g = lane >> 2;
    const int t = lane & 3;
    const int wrow = warp * 16;
    const float scale = 0.03125f;      // 1024^-0.5

    // ---- Q fragments (register resident, pre-scaled, tf32) ----
    float qa[8][4];
    {
        const float* qp0 = qkv + ((size_t)(b * TT + qt0 + wrow + g)) * C3 + h * HD;
        const float* qp1 = qp0 + 8 * (size_t)C3;
        #pragma unroll
        for (int kc = 0; kc < 8; kc++) {
            qa[kc][0] = to_tf32(qp0[kc * 8 + t]     * scale);
            qa[kc][1] = to_tf32(qp1[kc * 8 + t]     * scale);
            qa[kc][2] = to_tf32(qp0[kc * 8 + t + 4] * scale);
            qa[kc][3] = to_tf32(qp1[kc * 8 + t + 4] * scale);
        }
    }

    float o[8][4];
    #pragma unroll
    for (int i = 0; i < 8; i++)
        #pragma unroll
        for (int r = 0; r < 4; r++) o[i][r] = 0.f;
    float m0 = -1e30f, m1 = -1e30f, l0 = 0.f, l1 = 0.f;

    const int ntiles = 2 * qb + 2;
    for (int tile = 0; tile < ntiles; tile++) {
        const int kt0 = tile * 64;
        __syncthreads();

        // ---- stage K tile (rows=key, d-permuted cols) ----
        #pragma unroll
        for (int i = 0; i < 4; i++) {
            int idx = tid + i * 256;
            int r = idx >> 4;
            int c = (idx & 15) * 4;
            const float4 v = *(const float4*)(qkv + ((size_t)(b * TT + kt0 + r)) * C3 + CC + h * HD + c);
            float* kr = Ks + r * AST + (c & ~7) + ((c & 4) ? 1 : 0);
            kr[0] = to_tf32(v.x);
            kr[2] = to_tf32(v.y);
            kr[4] = to_tf32(v.z);
            kr[6] = to_tf32(v.w);
        }
        // ---- stage V transposed (rows=d, key-permuted cols) ----
        #pragma unroll
        for (int i = 0; i < 4; i++) {
            int cid = warp * 4 + i;
            int key = (cid & 1) * 32 + lane;
            int d0  = (cid >> 1) * 4;
            int pkey = (key & ~7) | (((key & 3) << 1) | ((key >> 2) & 1));
            const float4 v = *(const float4*)(qkv + ((size_t)(b * TT + kt0 + key)) * C3 + 2 * CC + h * HD + d0);
            Vts[(d0 + 0) * AST + pkey] = to_tf32(v.x);
            Vts[(d0 + 1) * AST + pkey] = to_tf32(v.y);
            Vts[(d0 + 2) * AST + pkey] = to_tf32(v.z);
            Vts[(d0 + 3) * AST + pkey] = to_tf32(v.w);
        }
        __syncthreads();

        // ---- S = Q K^T ----
        float s[8][4];
        #pragma unroll
        for (int i = 0; i < 8; i++)
            #pragma unroll
            for (int r = 0; r < 4; r++) s[i][r] = 0.f;
        #pragma unroll
        for (int kc = 0; kc < 8; kc++) {
            #pragma unroll
            for (int nt = 0; nt < 8; nt++) {
                float2 bb = *(const float2*)(Ks + (nt * 8 + g) * AST + kc * 8 + 2 * t);
                mma_tf32(s[nt][0], s[nt][1], s[nt][2], s[nt][3],
                         qa[kc][0], qa[kc][1], qa[kc][2], qa[kc][3],
                         bb.x, bb.y);
            }
        }

        // ---- causal mask (diagonal tiles only) ----
        if (tile >= 2 * qb) {
            const int q0 = qt0 + wrow + g;
            const int q1 = q0 + 8;
            #pragma unroll
            for (int nt = 0; nt < 8; nt++) {
                int kcol = kt0 + nt * 8 + 2 * t;
                if (kcol     > q0) s[nt][0] = -1e30f;
                if (kcol + 1 > q0) s[nt][1] = -1e30f;
                if (kcol     > q1) s[nt][2] = -1e30f;
                if (kcol + 1 > q1) s[nt][3] = -1e30f;
            }
        }

        // ---- online softmax (rows g and g+8) ----
        float mt0 = -1e30f, mt1 = -1e30f;
        #pragma unroll
        for (int nt = 0; nt < 8; nt++) {
            mt0 = fmaxf(mt0, fmaxf(s[nt][0], s[nt][1]));
            mt1 = fmaxf(mt1, fmaxf(s[nt][2], s[nt][3]));
        }
        mt0 = fmaxf(mt0, __shfl_xor_sync(0xffffffffu, mt0, 1));
        mt0 = fmaxf(mt0, __shfl_xor_sync(0xffffffffu, mt0, 2));
        mt1 = fmaxf(mt1, __shfl_xor_sync(0xffffffffu, mt1, 1));
        mt1 = fmaxf(mt1, __shfl_xor_sync(0xffffffffu, mt1, 2));

        const float mn0 = fmaxf(m0, mt0);
        const float mn1 = fmaxf(m1, mt1);
        const float c0 = __expf(m0 - mn0);
        const float c1 = __expf(m1 - mn1);
        float sum0 = 0.f, sum1 = 0.f;
        #pragma unroll
        for (int nt = 0; nt < 8; nt++) {
            s[nt][0] = __expf(s[nt][0] - mn0); sum0 += s[nt][0];
            s[nt][1] = __expf(s[nt][1] - mn0); sum0 += s[nt][1];
            s[nt][2] = __expf(s[nt][2] - mn1); sum1 += s[nt][2];
            s[nt][3] = __expf(s[nt][3] - mn1); sum1 += s[nt][3];
        }
        sum0 += __shfl_xor_sync(0xffffffffu, sum0, 1);
        sum0 += __shfl_xor_sync(0xffffffffu, sum0, 2);
        sum1 += __shfl_xor_sync(0xffffffffu, sum1, 1);
        sum1 += __shfl_xor_sync(0xffffffffu, sum1, 2);
        l0 = l0 * c0 + sum0;
        l1 = l1 * c1 + sum1;
        m0 = mn0; m1 = mn1;

        #pragma unroll
        for (int dt = 0; dt < 8; dt++) {
            o[dt][0] *= c0; o[dt][1] *= c0;
            o[dt][2] *= c1; o[dt][3] *= c1;
        }

        // ---- store P (key-permuted cols) ----
        const int pc0 = (t < 2) ? 4 * t     : 4 * t - 7;
        const int pc1 = (t < 2) ? 4 * t + 2 : 4 * t - 5;
        float* pr0 = Ps + (wrow + g) * AST;
        float* pr1 = pr0 + 8 * AST;
        #pragma unroll
        for (int nt = 0; nt < 8; nt++) {
            pr0[nt * 8 + pc0] = to_tf32(s[nt][0]);
            pr0[nt * 8 + pc1] = to_tf32(s[nt][1]);
            pr1[nt * 8 + pc0] = to_tf32(s[nt][2]);
            pr1[nt * 8 + pc1] = to_tf32(s[nt][3]);
        }
        __syncwarp();

        // ---- O += P V ----
        #pragma unroll
        for (int kc = 0; kc < 8; kc++) {
            float2 a01 = *(const float2*)(pr0 + kc * 8 + 2 * t);
            float2 a23 = *(const float2*)(pr1 + kc * 8 + 2 * t);
            #pragma unroll
            for (int dt = 0; dt < 8; dt++) {
                float2 bb = *(const float2*)(Vts + (dt * 8 + g) * AST + kc * 8 + 2 * t);
                mma_tf32(o[dt][0], o[dt][1], o[dt][2], o[dt][3],
                         a01.x, a23.x, a01.y, a23.y,
                         bb.x, bb.y);
            }
        }
    }

    // ---- epilogue ----
    const float inv0 = 1.f / l0;
    const float inv1 = 1.f / l1;
    const size_t ob0 = ((size_t)(b * TT + qt0 + wrow + g)) * CC + h * HD;
    const size_t ob1 = ob0 + 8 * (size_t)CC;
    #pragma unroll
    for (int dt = 0; dt < 8; dt++) {
        *(float2*)(out + ob0 + dt * 8 + 2 * t) = make_float2(o[dt][0] * inv0, o[dt][1] * inv0);
        *(float2*)(out + ob1 + dt * 8 + 2 * t) = make_float2(o[dt][2] * inv1, o[dt][3] * inv1);
    }
}

// ---------------------------------------------------------------------------
extern "C" void kernel_launch(void* const* d_in, const int* in_sizes, int n_in,
                              void* d_out, int out_size) {
    const float* x    = (const float*)d_in[0];   // [2,2048,1024]
    const float* Wqkv = (const float*)d_in[1];   // [1024,3072]
    const float* Wo   = (const float*)d_in[2];   // [1024,1024]
    float* out = (float*)d_out;                  // [2,2048,1024]

    float* qkv;  cudaGetSymbolAddress((void**)&qkv, g_qkv);
    float* att;  cudaGetSymbolAddress((void**)&att, g_att);

    // 1) qkv = x @ Wqkv
    tgemm<<<dim3(C3 / 128, ROWS / 128), 256>>>(x, Wqkv, qkv, ROWS, C3, CC);

    // 2) tensor-core causal flash attention
    const int SMEM_ATT = 256 * AST * (int)sizeof(float);   // 69632 B
    cudaFuncSetAttribute(attn_tc, cudaFuncAttributeMaxDynamicSharedMemorySize, SMEM_ATT);
    attn_tc<<<dim3(BB * HH, TT / 128), 256, SMEM_ATT>>>(qkv, att);

    // 3) out = att @ Wo
    tgemm<<<dim3(CC / 128, ROWS / 128), 256>>>(att, Wo, out, ROWS, CC, CC);
}

// round 4
// speedup vs baseline: 4.6591x; 1.3782x over previous
#include <cuda_runtime.h>
#include <cuda_bf16.h>
#include <cstdint>

// Problem constants
#define BB 2
#define TT 2048
#define CC 1024
#define HH 16
#define HD 64
#define ROWS (BB*TT)          // 4096
#define C3 (3*CC)             // 3072

// Scratch (allocation-free: __device__ globals)
__device__ float g_qkv[(size_t)ROWS * C3];    // tf32-rounded q|k|v
__device__ float g_att[(size_t)ROWS * CC];    // tf32-rounded attention out
__device__ float g_xr[(size_t)ROWS * CC];     // tf32-rounded x
__device__ float g_wqkvr[(size_t)CC * C3];    // tf32-rounded Wqkv
__device__ float g_wor[(size_t)CC * CC];      // tf32-rounded Wo

// ---------------------------------------------------------------------------
// helpers
// ---------------------------------------------------------------------------
__device__ __forceinline__ float to_tf32(float x) {
    float y;
    asm("cvt.rna.tf32.f32 %0, %1;" : "=f"(y) : "f"(x));
    return y;
}

__device__ __forceinline__ void mma_tf32(float& d0, float& d1, float& d2, float& d3,
                                         float a0, float a1, float a2, float a3,
                                         float b0, float b1) {
    asm volatile(
        "mma.sync.aligned.m16n8k8.row.col.f32.tf32.tf32.f32 "
        "{%0,%1,%2,%3}, {%4,%5,%6,%7}, {%8,%9}, {%0,%1,%2,%3};"
        : "+f"(d0), "+f"(d1), "+f"(d2), "+f"(d3)
        : "r"(__float_as_uint(a0)), "r"(__float_as_uint(a1)),
          "r"(__float_as_uint(a2)), "r"(__float_as_uint(a3)),
          "r"(__float_as_uint(b0)), "r"(__float_as_uint(b1)));
}

__device__ __forceinline__ void cp16(void* dst, const float* src) {
    uint32_t d = (uint32_t)__cvta_generic_to_shared(dst);
    asm volatile("cp.async.cg.shared.global [%0], [%1], 16;" :: "r"(d), "l"(src));
}
#define CP_COMMIT() asm volatile("cp.async.commit_group;")

// ---------------------------------------------------------------------------
// pre-round inputs to tf32 (RN) so GEMM/attention staging needs no cvt
// ---------------------------------------------------------------------------
__global__ void pre_round(const float4* __restrict__ in, float4* __restrict__ out, int n4) {
    int i = blockIdx.x * 256 + threadIdx.x;
    if (i < n4) {
        float4 v = in[i];
        v.x = to_tf32(v.x); v.y = to_tf32(v.y);
        v.z = to_tf32(v.z); v.w = to_tf32(v.w);
        out[i] = v;
    }
}

// ---------------------------------------------------------------------------
// tf32 tensor-core GEMM with cp.async 2-stage pipeline.
// Inputs MUST already be tf32-valued. Block tile 128x128x32, 8 warps.
// As[128][36] (36%32==4 -> A-frag LDS.32 banks 4g+t, conflict-free)
// Bs[32][136] (136%32==8 -> B-frag LDS.32 banks 8t+g, conflict-free)
// roundOut: round C to tf32 (for tensors feeding later MMA stages).
// ---------------------------------------------------------------------------
#define ASTR 36
#define BSTR 136
#define AS_SZ (128*ASTR)
#define BS_SZ (32*BSTR)

__global__ __launch_bounds__(256, 2) void tgemm(const float* __restrict__ A,
                                                const float* __restrict__ B,
                                                float* __restrict__ C,
                                                int M, int N, int K, int roundOut) {
    extern __shared__ float sm[];
    float* As = sm;                  // [2][AS_SZ]
    float* Bs = sm + 2 * AS_SZ;      // [2][BS_SZ]

    const int tid  = threadIdx.x;
    const int warp = tid >> 5;
    const int lane = tid & 31;
    const int g = lane >> 2;
    const int t = lane & 3;
    const int wm = (warp >> 2) * 64;
    const int wn = (warp & 3) * 32;
    const int row0 = blockIdx.y * 128;
    const int col0 = blockIdx.x * 128;

    float acc[4][4][4];
    #pragma unroll
    for (int i = 0; i < 4; i++)
        #pragma unroll
        for (int j = 0; j < 4; j++)
            #pragma unroll
            for (int r = 0; r < 4; r++) acc[i][j][r] = 0.f;

    const int NK = K >> 5;

    // producer
    auto prefetch = [&](int kt, int stage) {
        float* Ad = As + stage * AS_SZ;
        float* Bd = Bs + stage * BS_SZ;
        #pragma unroll
        for (int i = 0; i < 4; i++) {
            int id = tid + i * 256;
            int r = id >> 3, k4 = (id & 7) * 4;
            cp16(Ad + r * ASTR + k4, A + (size_t)(row0 + r) * K + kt + k4);
        }
        #pragma unroll
        for (int i = 0; i < 4; i++) {
            int id = tid + i * 256;
            int k = id >> 5, n4 = (id & 31) * 4;
            cp16(Bd + k * BSTR + n4, B + (size_t)(kt + k) * N + col0 + n4);
        }
        CP_COMMIT();
    };

    prefetch(0, 0);

    for (int it = 0; it < NK; it++) {
        const int stage = it & 1;
        if (it + 1 < NK) {
            prefetch((it + 1) * 32, stage ^ 1);
            asm volatile("cp.async.wait_group 1;");
        } else {
            asm volatile("cp.async.wait_group 0;");
        }
        __syncthreads();

        const float* Ac = As + stage * AS_SZ;
        const float* Bc = Bs + stage * BS_SZ;

        #pragma unroll
        for (int ks = 0; ks < 4; ks++) {
            const int k0 = ks * 8;
            float af[4][4];
            #pragma unroll
            for (int mt = 0; mt < 4; mt++) {
                int r = wm + mt * 16 + g;
                af[mt][0] = Ac[(r    ) * ASTR + k0 + t];
                af[mt][1] = Ac[(r + 8) * ASTR + k0 + t];
                af[mt][2] = Ac[(r    ) * ASTR + k0 + t + 4];
                af[mt][3] = Ac[(r + 8) * ASTR + k0 + t + 4];
            }
            float bf[4][2];
            #pragma unroll
            for (int nt = 0; nt < 4; nt++) {
                int c = wn + nt * 8 + g;
                bf[nt][0] = Bc[(k0 + t    ) * BSTR + c];
                bf[nt][1] = Bc[(k0 + t + 4) * BSTR + c];
            }
            #pragma unroll
            for (int mt = 0; mt < 4; mt++)
                #pragma unroll
                for (int nt = 0; nt < 4; nt++)
                    mma_tf32(acc[mt][nt][0], acc[mt][nt][1], acc[mt][nt][2], acc[mt][nt][3],
                             af[mt][0], af[mt][1], af[mt][2], af[mt][3],
                             bf[nt][0], bf[nt][1]);
        }
        __syncthreads();
    }

    #pragma unroll
    for (int mt = 0; mt < 4; mt++) {
        int r = row0 + wm + mt * 16 + g;
        #pragma unroll
        for (int nt = 0; nt < 4; nt++) {
            int c = col0 + wn + nt * 8 + 2 * t;
            float v0 = acc[mt][nt][0], v1 = acc[mt][nt][1];
            float v2 = acc[mt][nt][2], v3 = acc[mt][nt][3];
            if (roundOut) { v0 = to_tf32(v0); v1 = to_tf32(v1); v2 = to_tf32(v2); v3 = to_tf32(v3); }
            *(float2*)&C[(size_t)r * N + c]       = make_float2(v0, v1);
            *(float2*)&C[(size_t)(r + 8) * N + c] = make_float2(v2, v3);
        }
    }
}

// ---------------------------------------------------------------------------
// Tensor-core causal flash attention, cp.async double-buffered K/V.
// qkv holds tf32-valued floats (rounded by QKV-GEMM epilogue) -> no cvt here.
// Block: 128 query rows of one (b,h); 8 warps x 16 rows; key tiles of 64.
//   Ks[2][64][68]  (68%32==4  -> S B-frag banks 4g+t, conflict-free)
//   Vs[2][64][72]  (72%32==8  -> O B-frag banks 8t+g, conflict-free)
//   Ps[128][72]    (stores 8g+2t per half-warp; loads 8g+t: conflict-free)
// ---------------------------------------------------------------------------
#define KST 68
#define VST 72
#define PST 72
#define KS_SZ (64*KST)
#define VS_SZ (64*VST)

__global__ __launch_bounds__(256, 2) void attn_tc(const float* __restrict__ qkv,
                                                  float* __restrict__ out) {
    extern __shared__ float sm[];
    float* Ks = sm;                       // [2][KS_SZ]
    float* Vs = sm + 2 * KS_SZ;           // [2][VS_SZ]
    float* Ps = sm + 2 * KS_SZ + 2 * VS_SZ; // [128*PST]

    const int b   = blockIdx.x >> 4;
    const int h   = blockIdx.x & 15;
    const int qb  = (gridDim.y - 1) - blockIdx.y;   // heavy blocks first
    const int qt0 = qb * 128;
    const int tid  = threadIdx.x;
    const int warp = tid >> 5;
    const int lane = tid & 31;
    const int g = lane >> 2;
    const int t = lane & 3;
    const int wrow = warp * 16;
    const float scale = 0.03125f;         // 2^-5 exact: preserves tf32

    // ---- Q fragments (register resident, pre-scaled; qkv already tf32) ----
    float qa[8][4];
    {
        const float* qp0 = qkv + ((size_t)(b * TT + qt0 + wrow + g)) * C3 + h * HD;
        const float* qp1 = qp0 + 8 * (size_t)C3;
        #pragma unroll
        for (int kc = 0; kc < 8; kc++) {
            qa[kc][0] = qp0[kc * 8 + t]     * scale;
            qa[kc][1] = qp1[kc * 8 + t]     * scale;
            qa[kc][2] = qp0[kc * 8 + t + 4] * scale;
            qa[kc][3] = qp1[kc * 8 + t + 4] * scale;
        }
    }

    float o[8][4];
    #pragma unroll
    for (int i = 0; i < 8; i++)
        #pragma unroll
        for (int r = 0; r < 4; r++) o[i][r] = 0.f;
    float m0 = -1e30f, m1 = -1e30f, l0 = 0.f, l1 = 0.f;

    const int ntiles = 2 * qb + 2;

    auto prefetch = [&](int tile, int stage) {
        const int kt0 = tile * 64;
        const float* kb = qkv + ((size_t)(b * TT + kt0)) * C3 + CC + h * HD;
        const float* vb = kb + CC;
        float* Kd = Ks + stage * KS_SZ;
        float* Vd = Vs + stage * VS_SZ;
        #pragma unroll
        for (int i = 0; i < 4; i++) {
            int id = tid + i * 256;
            int r = id >> 4, c4 = (id & 15) * 4;
            cp16(Kd + r * KST + c4, kb + (size_t)r * C3 + c4);
            cp16(Vd + r * VST + c4, vb + (size_t)r * C3 + c4);
        }
        CP_COMMIT();
    };

    prefetch(0, 0);

    for (int tile = 0; tile < ntiles; tile++) {
        const int stage = tile & 1;
        const int kt0 = tile * 64;
        if (tile + 1 < ntiles) {
            prefetch(tile + 1, stage ^ 1);
            asm volatile("cp.async.wait_group 1;");
        } else {
            asm volatile("cp.async.wait_group 0;");
        }
        __syncthreads();

        const float* Kc = Ks + stage * KS_SZ;
        const float* Vc = Vs + stage * VS_SZ;

        // ---- S = Q K^T ----
        float s[8][4];
        #pragma unroll
        for (int i = 0; i < 8; i++)
            #pragma unroll
            for (int r = 0; r < 4; r++) s[i][r] = 0.f;
        #pragma unroll
        for (int kc = 0; kc < 8; kc++) {
            #pragma unroll
            for (int nt = 0; nt < 8; nt++) {
                const float* kr = Kc + (nt * 8 + g) * KST + kc * 8 + t;
                mma_tf32(s[nt][0], s[nt][1], s[nt][2], s[nt][3],
                         qa[kc][0], qa[kc][1], qa[kc][2], qa[kc][3],
                         kr[0], kr[4]);
            }
        }

        // ---- causal mask (diagonal tiles only) ----
        if (tile >= 2 * qb) {
            const int q0 = qt0 + wrow + g;
            const int q1 = q0 + 8;
            #pragma unroll
            for (int nt = 0; nt < 8; nt++) {
                int kcol = kt0 + nt * 8 + 2 * t;
                if (kcol     > q0) s[nt][0] = -1e30f;
                if (kcol + 1 > q0) s[nt][1] = -1e30f;
                if (kcol     > q1) s[nt][2] = -1e30f;
                if (kcol + 1 > q1) s[nt][3] = -1e30f;
            }
        }

        // ---- online softmax (rows g and g+8) ----
        float mt0 = -1e30f, mt1 = -1e30f;
        #pragma unroll
        for (int nt = 0; nt < 8; nt++) {
            mt0 = fmaxf(mt0, fmaxf(s[nt][0], s[nt][1]));
            mt1 = fmaxf(mt1, fmaxf(s[nt][2], s[nt][3]));
        }
        mt0 = fmaxf(mt0, __shfl_xor_sync(0xffffffffu, mt0, 1));
        mt0 = fmaxf(mt0, __shfl_xor_sync(0xffffffffu, mt0, 2));
        mt1 = fmaxf(mt1, __shfl_xor_sync(0xffffffffu, mt1, 1));
        mt1 = fmaxf(mt1, __shfl_xor_sync(0xffffffffu, mt1, 2));

        const float mn0 = fmaxf(m0, mt0);
        const float mn1 = fmaxf(m1, mt1);
        const float c0 = __expf(m0 - mn0);
        const float c1 = __expf(m1 - mn1);
        float sum0 = 0.f, sum1 = 0.f;
        #pragma unroll
        for (int nt = 0; nt < 8; nt++) {
            s[nt][0] = __expf(s[nt][0] - mn0); sum0 += s[nt][0];
            s[nt][1] = __expf(s[nt][1] - mn0); sum0 += s[nt][1];
            s[nt][2] = __expf(s[nt][2] - mn1); sum1 += s[nt][2];
            s[nt][3] = __expf(s[nt][3] - mn1); sum1 += s[nt][3];
        }
        sum0 += __shfl_xor_sync(0xffffffffu, sum0, 1);
        sum0 += __shfl_xor_sync(0xffffffffu, sum0, 2);
        sum1 += __shfl_xor_sync(0xffffffffu, sum1, 1);
        sum1 += __shfl_xor_sync(0xffffffffu, sum1, 2);
        l0 = l0 * c0 + sum0;
        l1 = l1 * c1 + sum1;
        m0 = mn0; m1 = mn1;

        #pragma unroll
        for (int dt = 0; dt < 8; dt++) {
            o[dt][0] *= c0; o[dt][1] *= c0;
            o[dt][2] *= c1; o[dt][3] *= c1;
        }

        // ---- store P (tf32-rounded) ----
        float* pr0 = Ps + (wrow + g) * PST;
        float* pr1 = pr0 + 8 * PST;
        #pragma unroll
        for (int nt = 0; nt < 8; nt++) {
            *(float2*)(pr0 + nt * 8 + 2 * t) = make_float2(to_tf32(s[nt][0]), to_tf32(s[nt][1]));
            *(float2*)(pr1 + nt * 8 + 2 * t) = make_float2(to_tf32(s[nt][2]), to_tf32(s[nt][3]));
        }
        __syncwarp();

        // ---- O += P V ----
        #pragma unroll
        for (int kc = 0; kc < 8; kc++) {
            float a0 = pr0[kc * 8 + t];
            float a1 = pr1[kc * 8 + t];
            float a2 = pr0[kc * 8 + t + 4];
            float a3 = pr1[kc * 8 + t + 4];
            #pragma unroll
            for (int dt = 0; dt < 8; dt++) {
                const float* vr0 = Vc + (kc * 8 + t    ) * VST + dt * 8 + g;
                const float* vr1 = Vc + (kc * 8 + t + 4) * VST + dt * 8 + g;
                mma_tf32(o[dt][0], o[dt][1], o[dt][2], o[dt][3],
                         a0, a1, a2, a3, vr0[0], vr1[0]);
            }
        }
        __syncthreads();
    }

    // ---- epilogue (tf32-rounded for the O-GEMM) ----
    const float inv0 = 1.f / l0;
    const float inv1 = 1.f / l1;
    const size_t ob0 = ((size_t)(b * TT + qt0 + wrow + g)) * CC + h * HD;
    const size_t ob1 = ob0 + 8 * (size_t)CC;
    #pragma unroll
    for (int dt = 0; dt < 8; dt++) {
        *(float2*)(out + ob0 + dt * 8 + 2 * t) =
            make_float2(to_tf32(o[dt][0] * inv0), to_tf32(o[dt][1] * inv0));
        *(float2*)(out + ob1 + dt * 8 + 2 * t) =
            make_float2(to_tf32(o[dt][2] * inv1), to_tf32(o[dt][3] * inv1));
    }
}

// ---------------------------------------------------------------------------
extern "C" void kernel_launch(void* const* d_in, const int* in_sizes, int n_in,
                              void* d_out, int out_size) {
    const float* x    = (const float*)d_in[0];   // [2,2048,1024]
    const float* Wqkv = (const float*)d_in[1];   // [1024,3072]
    const float* Wo   = (const float*)d_in[2];   // [1024,1024]
    float* out = (float*)d_out;                  // [2,2048,1024]

    float *qkv, *att, *xr, *wqkvr, *wor;
    cudaGetSymbolAddress((void**)&qkv,   g_qkv);
    cudaGetSymbolAddress((void**)&att,   g_att);
    cudaGetSymbolAddress((void**)&xr,    g_xr);
    cudaGetSymbolAddress((void**)&wqkvr, g_wqkvr);
    cudaGetSymbolAddress((void**)&wor,   g_wor);

    // 0) pre-round inputs to tf32
    pre_round<<<(ROWS * CC / 4 + 255) / 256, 256>>>((const float4*)x, (float4*)xr, ROWS * CC / 4);
    pre_round<<<(CC * C3 / 4 + 255) / 256, 256>>>((const float4*)Wqkv, (float4*)wqkvr, CC * C3 / 4);
    pre_round<<<(CC * CC / 4 + 255) / 256, 256>>>((const float4*)Wo, (float4*)wor, CC * CC / 4);

    const int SMEM_G = (2 * AS_SZ + 2 * BS_SZ) * (int)sizeof(float);      // 71680
    const int SMEM_A = (2 * KS_SZ + 2 * VS_SZ + 128 * PST) * (int)sizeof(float); // 108544
    static int inited = 0;
    if (!inited) {
        cudaFuncSetAttribute(tgemm,   cudaFuncAttributeMaxDynamicSharedMemorySize, SMEM_G);
        cudaFuncSetAttribute(attn_tc, cudaFuncAttributeMaxDynamicSharedMemorySize, SMEM_A);
        inited = 1;
    }

    // 1) qkv = x @ Wqkv  (epilogue rounds to tf32 for attention)
    tgemm<<<dim3(C3 / 128, ROWS / 128), 256, SMEM_G>>>(xr, wqkvr, qkv, ROWS, C3, CC, 1);

    // 2) tensor-core causal flash attention
    attn_tc<<<dim3(BB * HH, TT / 128), 256, SMEM_A>>>(qkv, att);

    // 3) out = att @ Wo  (full-precision output)
    tgemm<<<dim3(CC / 128, ROWS / 128), 256, SMEM_G>>>(att, wor, out, ROWS, CC, CC, 0);
}